// round 9
// baseline (speedup 1.0000x reference)
#include <cuda_runtime.h>
#include <cstdint>

// CostVolumeLayer3D, B=2 C=64 D=32 H=64 W=64, R=2.
// out[b, ch(s,dsh), d, h, w] = (1/125) * sum_c x1[b,c,d,h,w] * x2[b,c,d-dsh,h-i_s,w-j_s]
//   s in [-4,4], dsh in [-2,2], (i_s,j_s) = (min(2,s+2), max(-2,s-2)),
//   ch = (5s+dsh) mod 125. Channels 23..102 are identically zero.
// 256-thr CTA (8 h-rows x 32 w-pairs), thread = w-pair x d-pair, 90 f32x2 acc.
// 8-buffer cp.async pipeline, prefetch distance 5, barrier every 2 channels.
// x1 streamed through registers (LDG.64, one channel ahead).

typedef unsigned long long ull;
#define LD64(p) (*reinterpret_cast<const ull*>(p))

static __device__ __forceinline__ void cp16(uint32_t dst, const float* src, int vsz) {
    asm volatile("cp.async.cg.shared.global [%0], [%1], 16, %2;"
                 :: "r"(dst), "l"(src), "r"(vsz));
}
static __device__ __forceinline__ ull pk2(uint32_t lo, uint32_t hi) {
    ull r; asm("mov.b64 %0, {%1,%2};" : "=l"(r) : "r"(lo), "r"(hi)); return r;
}
static __device__ __forceinline__ void unpk(uint32_t& lo, uint32_t& hi, ull v) {
    asm("mov.b64 {%0,%1}, %2;" : "=r"(lo), "=r"(hi) : "l"(v));
}
static __device__ __forceinline__ void fma2(ull& acc, ull a, ull b) {
    asm("fma.rn.f32x2 %0, %1, %2, %0;" : "+l"(acc) : "l"(a), "l"(b));
}
static __device__ __forceinline__ ull mul2(ull a, ull b) {
    ull r; asm("mul.rn.f32x2 %0, %1, %2;" : "=l"(r) : "l"(a), "l"(b)); return r;
}

// Per-buffer smem (floats): x2 only, 6 planes * (12 rows * 72 cols) = 5184
// (20736 B); smem col = global_w + 4 (W halo cols 2,3,68,69). 8 buffers.
extern __shared__ float sm[];

__global__ void __launch_bounds__(256, 1)
cv3d_kernel(const float* __restrict__ x1, const float* __restrict__ x2,
            float* __restrict__ out)
{
    const int tid = threadIdx.x;
    const int hl  = tid >> 5;           // 0..7: h row within tile (warp = one row)
    const int w   = (tid & 31) * 2;     // even w; thread owns (w, w+1)
    const int h0  = blockIdx.x * 8;
    const int d0  = blockIdx.y * 2;
    const int b   = blockIdx.z;
    const int gh  = h0 + hl;

    const float* x1b = x1 + (size_t)b * 8388608;
    const float* x2b = x2 + (size_t)b * 8388608;
    const uint32_t smb = (uint32_t)__cvta_generic_to_shared(sm);

    // ---- cp.async chunk table: 1152 x2 chunks, 5 per thread (k=4: tid<128) ----
    const float* csrc[5]; uint32_t cdst[5]; int cvsz[5];
    #pragma unroll
    for (int k = 0; k < 5; ++k) {
        int q = tid + 256 * k;
        int pl = q / 192, r = q % 192, row = r >> 4, cw = r & 15;
        int gd = d0 - 2 + pl, ghr = h0 - 2 + row;
        bool inr = ((unsigned)gd < 32u) && ((unsigned)ghr < 64u);
        cvsz[k] = inr ? 16 : 0;         // src-size 0 => zero-fill (D/H halo)
        csrc[k] = x2b + (size_t)(inr ? gd : 0) * 4096 + (inr ? ghr : 0) * 64 + cw * 4;
        cdst[k] = smb + (uint32_t)(pl * 864 + row * 72 + 4 + cw * 4) * 4u;
    }
    const bool k4 = (tid < 128);

#define XFETCH(CC, BUF) do {                                                     \
    const uint32_t _o = (uint32_t)(BUF) * 20736u;                                \
    const size_t _c = (size_t)(CC) * 131072;                                     \
    cp16(cdst[0] + _o, csrc[0] + _c, cvsz[0]);                                   \
    cp16(cdst[1] + _o, csrc[1] + _c, cvsz[1]);                                   \
    cp16(cdst[2] + _o, csrc[2] + _c, cvsz[2]);                                   \
    cp16(cdst[3] + _o, csrc[3] + _c, cvsz[3]);                                   \
    if (k4) cp16(cdst[4] + _o, csrc[4] + _c, cvsz[4]);                           \
    asm volatile("cp.async.commit_group;");                                      \
} while (0)

    // ---- prologue: prefetch channels 0..4 into buffers 0..4 ----
    XFETCH(0, 0); XFETCH(1, 1); XFETCH(2, 2); XFETCH(3, 3); XFETCH(4, 4);

    // ---- zero W-halo columns of all 8 buffers (image edge => always 0) ----
    for (int q = tid; q < 576; q += 256) {
        int buf = q / 72, r = q % 72, pl = r / 12, row = r % 12;
        float* hp = sm + buf * 5184 + pl * 864 + row * 72;
        hp[2] = 0.f; hp[3] = 0.f; hp[68] = 0.f; hp[69] = 0.f;
    }

    // ---- zero the 80 never-written output channels (23..102) for this tile ----
    {
        float* zb = out + (size_t)b * 16384000 + (size_t)23 * 131072
                        + (size_t)d0 * 4096 + (size_t)h0 * 64;
        int dd = tid >> 7, row = (tid >> 4) & 7, cw = tid & 15;
        float* base = zb + dd * 4096 + row * 64 + cw * 4;
        const float4 z = make_float4(0.f, 0.f, 0.f, 0.f);
        #pragma unroll 4
        for (int ch = 0; ch < 80; ++ch)
            *reinterpret_cast<float4*>(base + (size_t)ch * 131072) = z;
    }

    // ---- x1 register stream, one channel ahead ----
    const float* x1p = x1b + (size_t)d0 * 4096 + (size_t)gh * 64 + w;
    ull A0 = LD64(x1p), A1 = LD64(x1p + 4096);

    // ---- accumulators: [d-index][dsh+2][s+4], f32x2 lanes = (w, w+1) ----
    ull acc[2][5][9];
    #pragma unroll
    for (int a = 0; a < 2; ++a)
        #pragma unroll
        for (int u = 0; u < 5; ++u)
            #pragma unroll
            for (int v = 0; v < 9; ++v) acc[a][u][v] = 0ull;

    int cb = 0;   // buffer of channel c
    int pb = 5;   // buffer receiving channel c+5

    #pragma unroll 2
    for (int c = 0; c < 64; ++c) {
        // barrier + visibility only on even channels (wait 3 => channels <= c+1
        // complete for THIS thread; barrier publishes across threads).
        if ((c & 1) == 0) {
            if      (c < 60)  asm volatile("cp.async.wait_group 3;");
            else if (c == 60) asm volatile("cp.async.wait_group 2;");
            else              asm volatile("cp.async.wait_group 0;");
            __syncthreads();
        }

        ull N0 = 0, N1 = 0;
        if (c < 63) {
            const float* nx = x1p + (size_t)(c + 1) * 131072;
            N0 = LD64(nx); N1 = LD64(nx + 4096);
        }
        if (c < 59) XFETCH(c + 5, pb);

        const float* xw = sm + cb * 5184 + hl * 72 + (w + 4); // (row gh-2, col w)
        #pragma unroll
        for (int p = 0; p < 6; ++p) {                 // x2 plane gd = d0-2+p
            const float* pp = xw + p * 864;
            ull f0 = LD64(pp - 2);   // row gh-2: cols w-2,w-1
            ull f2 = LD64(pp);       //            cols w,  w+1
            ull f4 = LD64(pp + 2);   //            cols w+2,w+3
            ull l1 = LD64(pp + 74);  // row gh-1, cols w+2,w+3
            ull l2 = LD64(pp + 146); // row gh
            ull l3 = LD64(pp + 218); // row gh+1
            ull l4 = LD64(pp + 290); // row gh+2
            uint32_t f0lo, f0hi, f2lo, f2hi, f4lo, f4hi;
            unpk(f0lo, f0hi, f0); unpk(f2lo, f2hi, f2); unpk(f4lo, f4hi, f4);
            ull bb[9];
            bb[0] = l4;                 // s=-4
            bb[1] = l3;                 // s=-3
            bb[2] = l2;                 // s=-2
            bb[3] = l1;                 // s=-1
            bb[4] = f4;                 // s= 0
            bb[5] = pk2(f2hi, f4lo);    // s= 1
            bb[6] = f2;                 // s= 2
            bb[7] = pk2(f0hi, f2lo);    // s= 3
            bb[8] = f0;                 // s= 4
            if (p <= 4) {               // voxel d0:   u = 4-p
                #pragma unroll
                for (int v = 0; v < 9; ++v) fma2(acc[0][4 - p][v], A0, bb[v]);
            }
            if (p >= 1) {               // voxel d0+1: u = 5-p
                #pragma unroll
                for (int v = 0; v < 9; ++v) fma2(acc[1][5 - p][v], A1, bb[v]);
            }
        }

        A0 = N0; A1 = N1;
        cb = (cb == 7) ? 0 : cb + 1;
        pb = (pb == 7) ? 0 : pb + 1;
    }

    // ---- epilogue: scale by 1/125 and store ----
    const uint32_t invb = __float_as_uint(1.0f / 125.0f);
    const ull invv = pk2(invb, invb);
    float* ob = out + (size_t)b * 16384000 + (size_t)d0 * 4096
                    + (size_t)gh * 64 + w;
    #pragma unroll
    for (int a = 0; a < 2; ++a)
        #pragma unroll
        for (int u = 0; u < 5; ++u)
            #pragma unroll
            for (int v = 0; v < 9; ++v) {
                int ch = (5 * (v - 4) + (u - 2)) % 125;
                if (ch < 0) ch += 125;
                ull r = mul2(acc[a][u][v], invv);
                *reinterpret_cast<ull*>(ob + (size_t)ch * 131072 + a * 4096) = r;
            }
}

extern "C" void kernel_launch(void* const* d_in, const int* in_sizes, int n_in,
                              void* d_out, int out_size) {
    const float* x1 = (const float*)d_in[0];
    const float* x2 = (const float*)d_in[1];
    float* out = (float*)d_out;
    cudaFuncSetAttribute(cv3d_kernel,
                         cudaFuncAttributeMaxDynamicSharedMemorySize, 165888);
    cv3d_kernel<<<dim3(8, 16, 2), 256, 165888>>>(x1, x2, out);
}

// round 10
// speedup vs baseline: 1.1506x; 1.1506x over previous
#include <cuda_runtime.h>
#include <cstdint>

// CostVolumeLayer3D, B=2 C=64 D=32 H=64 W=64, R=2.
// out[b, ch(s,dsh), d, h, w] = (1/125) * sum_c x1[b,c,d,h,w] * x2[b,c,d-dsh,h-i_s,w-j_s]
//   s in [-4,4], dsh in [-2,2], (i_s,j_s) = (min(2,s+2), max(-2,s-2)),
//   ch = (5s+dsh) mod 125. Channels 23..102 are identically zero.
// 128-thr CTA (4 h-rows), thread = w-pair x d-pair, 90 f32x2 accumulators.
// 6-buffer cp.async pipeline (distance 5, wait_group 4) + EXPLICIT plane-level
// software pipeline: LDS for plane p+1 issued before FMAs of plane p.

typedef unsigned long long ull;
#define LD64(p) (*reinterpret_cast<const ull*>(p))

static __device__ __forceinline__ void cp16(uint32_t dst, const float* src, int vsz) {
    asm volatile("cp.async.cg.shared.global [%0], [%1], 16, %2;"
                 :: "r"(dst), "l"(src), "r"(vsz));
}
static __device__ __forceinline__ ull pk2(uint32_t lo, uint32_t hi) {
    ull r; asm("mov.b64 %0, {%1,%2};" : "=l"(r) : "r"(lo), "r"(hi)); return r;
}
static __device__ __forceinline__ void unpk(uint32_t& lo, uint32_t& hi, ull v) {
    asm("mov.b64 {%0,%1}, %2;" : "=r"(lo), "=r"(hi) : "l"(v));
}
static __device__ __forceinline__ void fma2(ull& acc, ull a, ull b) {
    asm("fma.rn.f32x2 %0, %1, %2, %0;" : "+l"(acc) : "l"(a), "l"(b));
}
static __device__ __forceinline__ ull mul2(ull a, ull b) {
    ull r; asm("mul.rn.f32x2 %0, %1, %2;" : "=l"(r) : "l"(a), "l"(b)); return r;
}

// Load the 7 b-values of one x2 plane from smem (pp = row gh-2, col w).
static __device__ __forceinline__ void loadp(ull t[7], const float* pp) {
    t[0] = LD64(pp - 2);    // row gh-2: cols w-2,w-1
    t[1] = LD64(pp);        //            cols w,  w+1
    t[2] = LD64(pp + 2);    //            cols w+2,w+3
    t[3] = LD64(pp + 74);   // row gh-1, cols w+2,w+3
    t[4] = LD64(pp + 146);  // row gh
    t[5] = LD64(pp + 218);  // row gh+1
    t[6] = LD64(pp + 290);  // row gh+2
}

static __device__ __forceinline__ void planefma(
    const ull t[7], int p, ull A0, ull A1, ull acc[2][5][9])
{
    uint32_t f0lo, f0hi, f2lo, f2hi, f4lo, f4hi;
    unpk(f0lo, f0hi, t[0]); unpk(f2lo, f2hi, t[1]); unpk(f4lo, f4hi, t[2]);
    ull bb[9];
    bb[0] = t[6];               // s=-4
    bb[1] = t[5];               // s=-3
    bb[2] = t[4];               // s=-2
    bb[3] = t[3];               // s=-1
    bb[4] = t[2];               // s= 0
    bb[5] = pk2(f2hi, f4lo);    // s= 1
    bb[6] = t[1];               // s= 2
    bb[7] = pk2(f0hi, f2lo);    // s= 3
    bb[8] = t[0];               // s= 4
    if (p <= 4) {               // voxel d0:   u = 4-p
        #pragma unroll
        for (int v = 0; v < 9; ++v) fma2(acc[0][4 - p][v], A0, bb[v]);
    }
    if (p >= 1) {               // voxel d0+1: u = 5-p
        #pragma unroll
        for (int v = 0; v < 9; ++v) fma2(acc[1][5 - p][v], A1, bb[v]);
    }
}

// Per-buffer smem layout (floats), 6 buffers (BUF = 3968 floats = 15872 B):
//   x2: 6 planes * (8 rows * 72 cols); smem col = global_w + 4 (halo cols 2,3,68,69)
//   x1 at +3456: 2 planes * (4 rows * 64 cols)
extern __shared__ float sm[];

__global__ void __launch_bounds__(128, 2)
cv3d_kernel(const float* __restrict__ x1, const float* __restrict__ x2,
            float* __restrict__ out)
{
    const int tid = threadIdx.x;
    const int hl  = tid >> 5;           // 0..3: h row (warp = one row)
    const int w   = (tid & 31) * 2;     // even w; thread owns (w, w+1)
    const int h0  = blockIdx.x * 4;
    const int d0  = blockIdx.y * 2;
    const int b   = blockIdx.z;

    const float* x1b = x1 + (size_t)b * 8388608;
    const float* x2b = x2 + (size_t)b * 8388608;
    const uint32_t smb = (uint32_t)__cvta_generic_to_shared(sm);

    // ---- compact cp.async geometry. x2 chunk q = tid + 128k (k=0..5):
    //      plane = k, row = tid>>4, cw = tid&15. x1 chunk: k=6.
    const int crow = tid >> 4, ccw = tid & 15;
    const int ghl  = h0 - 2 + crow;
    const bool ghok = ((unsigned)ghl < 64u);
    const float* srow = x2b + (size_t)(ghok ? ghl : 0) * 64 + ccw * 4;
    const uint32_t cdst0 = smb + (uint32_t)(crow * 72 + 4 + ccw * 4) * 4u;
    int gdo[6], vz[6];
    #pragma unroll
    for (int k = 0; k < 6; ++k) {
        int gd = d0 - 2 + k;
        vz[k]  = (ghok && (unsigned)gd < 32u) ? 16 : 0;
        int gdc = gd < 0 ? 0 : (gd > 31 ? 31 : gd);
        gdo[k] = gdc * 4096;
    }
    const int xa = tid >> 6, xrow = (tid >> 4) & 3, xcw = tid & 15;
    const float* xsrc = x1b + (size_t)(d0 + xa) * 4096
                            + (size_t)(h0 + xrow) * 64 + xcw * 4;
    const uint32_t xdst = smb + (uint32_t)(3456 + xa * 256 + xrow * 64 + xcw * 4) * 4u;

#define XFETCH(CC, BUF) do {                                                     \
    const uint32_t _o = (uint32_t)(BUF) * 15872u;                                \
    const size_t _c = (size_t)(CC) * 131072;                                     \
    _Pragma("unroll")                                                            \
    for (int _k = 0; _k < 6; ++_k)                                               \
        cp16(cdst0 + (uint32_t)_k * 2304u + _o, srow + _c + gdo[_k], vz[_k]);    \
    cp16(xdst + _o, xsrc + _c, 16);                                              \
    asm volatile("cp.async.commit_group;");                                      \
} while (0)

    // ---- prologue: prefetch channels 0..4 into buffers 0..4 ----
    XFETCH(0, 0); XFETCH(1, 1); XFETCH(2, 2); XFETCH(3, 3); XFETCH(4, 4);

    // ---- zero W-halo columns of all 6 buffers (image edge => always 0) ----
    for (int q = tid; q < 288; q += 128) {
        int buf = q / 48, r = q % 48, pl = r >> 3, row = r & 7;
        float* hp = sm + buf * 3968 + pl * 576 + row * 72;
        hp[2] = 0.f; hp[3] = 0.f; hp[68] = 0.f; hp[69] = 0.f;
    }

    // ---- zero the 80 never-written output channels (23..102) for this tile ----
    {
        float* zb = out + (size_t)b * 16384000 + (size_t)23 * 131072
                        + (size_t)d0 * 4096 + (size_t)h0 * 64;
        int dd = (tid >> 6) & 1, row = (tid >> 4) & 3, cw = tid & 15;
        float* base = zb + dd * 4096 + row * 64 + cw * 4;
        const float4 z = make_float4(0.f, 0.f, 0.f, 0.f);
        #pragma unroll 4
        for (int ch = 0; ch < 80; ++ch)
            *reinterpret_cast<float4*>(base + (size_t)ch * 131072) = z;
    }

    // ---- accumulators: [d-index][dsh+2][s+4], f32x2 lanes = (w, w+1) ----
    ull acc[2][5][9];
    #pragma unroll
    for (int a = 0; a < 2; ++a)
        #pragma unroll
        for (int u = 0; u < 5; ++u)
            #pragma unroll
            for (int v = 0; v < 9; ++v) acc[a][u][v] = 0ull;

    int cb = 0;   // buffer of channel c
    int pb = 5;   // buffer receiving channel c+5

    #pragma unroll 1
    for (int c = 0; c < 64; ++c) {
        if      (c < 60)  asm volatile("cp.async.wait_group 4;");
        else if (c == 60) asm volatile("cp.async.wait_group 3;");
        else if (c == 61) asm volatile("cp.async.wait_group 2;");
        else if (c == 62) asm volatile("cp.async.wait_group 1;");
        else              asm volatile("cp.async.wait_group 0;");
        __syncthreads();

        if (c < 59) XFETCH(c + 5, pb);

        const float* base = sm + cb * 3968;
        const float* xw = base + hl * 72 + (w + 4);     // (row gh-2, col w)
        const float* ax = base + 3456 + hl * 64 + w;
        const ull A0 = LD64(ax);                        // x1 (d0,   gh)
        const ull A1 = LD64(ax + 256);                  // x1 (d0+1, gh)

        // ---- plane-level software pipeline: load p+1 before computing p ----
        ull bufA[7], bufB[7];
        loadp(bufA, xw);                                // plane 0
        #pragma unroll
        for (int p = 0; p < 6; ++p) {
            ull* cur = (p & 1) ? bufB : bufA;
            ull* nxt = (p & 1) ? bufA : bufB;
            if (p < 5) loadp(nxt, xw + (p + 1) * 576);
            planefma(cur, p, A0, A1, acc);
        }

        cb = (cb == 5) ? 0 : cb + 1;
        pb = (pb == 5) ? 0 : pb + 1;
    }

    // ---- epilogue: scale by 1/125 and store ----
    const uint32_t invb = __float_as_uint(1.0f / 125.0f);
    const ull invv = pk2(invb, invb);
    float* ob = out + (size_t)b * 16384000 + (size_t)d0 * 4096
                    + (size_t)(h0 + hl) * 64 + w;
    #pragma unroll
    for (int a = 0; a < 2; ++a)
        #pragma unroll
        for (int u = 0; u < 5; ++u)
            #pragma unroll
            for (int v = 0; v < 9; ++v) {
                int ch = (5 * (v - 4) + (u - 2)) % 125;
                if (ch < 0) ch += 125;
                ull r = mul2(acc[a][u][v], invv);
                *reinterpret_cast<ull*>(ob + (size_t)ch * 131072 + a * 4096) = r;
            }
}

extern "C" void kernel_launch(void* const* d_in, const int* in_sizes, int n_in,
                              void* d_out, int out_size) {
    const float* x1 = (const float*)d_in[0];
    const float* x2 = (const float*)d_in[1];
    float* out = (float*)d_out;
    cudaFuncSetAttribute(cv3d_kernel,
                         cudaFuncAttributeMaxDynamicSharedMemorySize, 95232);
    cv3d_kernel<<<dim3(16, 16, 2), 128, 95232>>>(x1, x2, out);
}